// round 6
// baseline (speedup 1.0000x reference)
#include <cuda_runtime.h>
#include <math.h>

// Problem constants
#define BATCH   64
#define IN_D    256
#define MEM_D   128
#define NSLOT   4096
#define CPB     8                  // chunks (blocks) per batch -> single wave
#define CHUNK   (NSLOT / CPB)      // 512 rows per block

// -------- scratch (no device allocations allowed) --------
__device__ float g_v [BATCH * MEM_D];
__device__ float g_wq[BATCH * MEM_D];
__device__ float g_rq[BATCH * MEM_D];
__device__ float g_s [BATCH];
__device__ float g_rop[BATCH * CPB * MEM_D];   // per-chunk read_out partials

__device__ float g_pm1[BATCH * CPB];
__device__ float g_pz1[BATCH * CPB];
__device__ float g_pm2[BATCH * CPB];
__device__ float g_pz2[BATCH * CPB];
__device__ float g_ps2[BATCH * CPB];
__device__ int   g_cnt1[BATCH];                // zero-init; reset by out_kernel
__device__ int   g_cnt2[BATCH];

__device__ __forceinline__ float warpSum(float v) {
#pragma unroll
    for (int o = 16; o; o >>= 1) v += __shfl_xor_sync(0xffffffffu, v, o);
    return v;
}
__device__ __forceinline__ float warpMax(float v) {
#pragma unroll
    for (int o = 16; o; o >>= 1) v = fmaxf(v, __shfl_xor_sync(0xffffffffu, v, o));
    return v;
}
// block reduce for 256 threads (8 warps)
__device__ __forceinline__ float blockSum(float v, float* sred) {
    v = warpSum(v);
    if ((threadIdx.x & 31) == 0) sred[threadIdx.x >> 5] = v;
    __syncthreads();
    float r = sred[0];
#pragma unroll
    for (int i = 1; i < 8; i++) r += sred[i];
    __syncthreads();
    return r;
}
__device__ __forceinline__ float blockMax(float v, float* sred) {
    v = warpMax(v);
    if ((threadIdx.x & 31) == 0) sred[threadIdx.x >> 5] = v;
    __syncthreads();
    float r = sred[0];
#pragma unroll
    for (int i = 1; i < 8; i++) r = fmaxf(r, sred[i]);
    __syncthreads();
    return r;
}

// ---------------------------------------------------------------------------
// Kernel 1: projections, NO redundant weight reads.
// grid = 24 (3 matrices x 8 batch-groups of 8), block 256.
// Thread (o = t&127, bl = t>>7) computes 4 batches' outputs for column o:
// 4 independent 256-FMA chains, W read once per block (coalesced).
// ---------------------------------------------------------------------------
__global__ void __launch_bounds__(256)
proj_kernel(const float* __restrict__ x,
            const float* __restrict__ Ww, const float* __restrict__ bw,
            const float* __restrict__ Wq, const float* __restrict__ bq,
            const float* __restrict__ Wr, const float* __restrict__ br) {
    const int m  = blockIdx.x >> 3;          // 0..2
    const int bg = blockIdx.x & 7;           // batch group (8 batches)
    const int t  = threadIdx.x;

    const float* W    = (m == 0) ? Ww : ((m == 1) ? Wq : Wr);
    const float* bias = (m == 0) ? bw : ((m == 1) ? bq : br);
    float* dst        = (m == 0) ? g_v : ((m == 1) ? g_wq : g_rq);

    __shared__ float sx[8][IN_D];            // 8 KB
    {
        const float* xg = x + (size_t)bg * 8 * IN_D;
#pragma unroll
        for (int i = 0; i < 8; i++)
            ((float*)sx)[t + i * 256] = xg[t + i * 256];
    }
    __syncthreads();

    const int o  = t & 127;
    const int bl = t >> 7;                   // 0 or 1 -> batches bl*4..bl*4+3
    float a0 = 0.f, a1 = 0.f, a2 = 0.f, a3 = 0.f;
#pragma unroll 8
    for (int k = 0; k < IN_D; k++) {
        const float wv = W[k * MEM_D + o];
        a0 = fmaf(sx[bl * 4 + 0][k], wv, a0);
        a1 = fmaf(sx[bl * 4 + 1][k], wv, a1);
        a2 = fmaf(sx[bl * 4 + 2][k], wv, a2);
        a3 = fmaf(sx[bl * 4 + 3][k], wv, a3);
    }
    const float bv = bias[o];
    const int b0 = bg * 8 + bl * 4;
    dst[(b0 + 0) * MEM_D + o] = a0 + bv;
    dst[(b0 + 1) * MEM_D + o] = a1 + bv;
    dst[(b0 + 2) * MEM_D + o] = a2 + bv;
    dst[(b0 + 3) * MEM_D + o] = a3 + bv;
}

// ---------------------------------------------------------------------------
// Kernel 2: FUSED dots + dual-softmax + accumulation, SINGLE WAVE.
// grid = 512 (64 x 8 chunks), block 256, 4 blocks/SM -> all resident.
// Phase 1 streams the 256KB slice (coalesced, fills L2); phase 2 re-reads it
// in REVERSE order (newest-first: highest L2-residency chance) with __ldcs
// (evict-first: phase-2 misses don't evict other blocks' pending re-reads).
// Counters assumed 0 on entry (reset by out_kernel for next replay).
// ---------------------------------------------------------------------------
__global__ void __launch_bounds__(256, 4)
fused_kernel(const float* __restrict__ mem) {
    const int b  = blockIdx.x >> 3;
    const int ch = blockIdx.x & 7;
    const int bi = blockIdx.x;
    const int t  = threadIdx.x;
    const int lane = t & 31, w = t >> 5;      // 8 warps
    const int s = lane & 7, rsub = lane >> 3; // quarter-warp layout

    __shared__ float  sd1[CHUNK];             // d1 -> ww -> c
    __shared__ float  sd2[CHUNK];             // d2 -> rl
    __shared__ float  swq[MEM_D];
    __shared__ float  srq[MEM_D];
    __shared__ float  sred[8];
    __shared__ float  sbc[2];
    __shared__ float4 racc[256];

    if (t < MEM_D) {
        swq[t] = g_wq[b * MEM_D + t];
        srq[t] = g_rq[b * MEM_D + t];
    }
    __syncthreads();

    // per-thread query slices (cols (j*8+s)*4 .. +3)
    float4 q4[4], r4[4];
#pragma unroll
    for (int j = 0; j < 4; j++) {
        q4[j] = reinterpret_cast<const float4*>(swq)[j * 8 + s];
        r4[j] = reinterpret_cast<const float4*>(srq)[j * 8 + s];
    }

    const float4* mb = reinterpret_cast<const float4*>(mem) +
                       ((size_t)b * NSLOT + (size_t)ch * CHUNK) * 32;

    // ---- Phase 1: coalesced dots d1 = mem.wq, d2 = mem.rq ----
#pragma unroll 2
    for (int it = 0; it < 16; it++) {
        const int r0 = it * 32 + w * 4 + rsub;
        const float4* grow = mb + (size_t)r0 * 32;
        float a = 0.0f, c = 0.0f;
#pragma unroll
        for (int j = 0; j < 4; j++) {
            const float4 m = grow[j * 8 + s];
            a = fmaf(m.x, q4[j].x, a); a = fmaf(m.y, q4[j].y, a);
            a = fmaf(m.z, q4[j].z, a); a = fmaf(m.w, q4[j].w, a);
            c = fmaf(m.x, r4[j].x, c); c = fmaf(m.y, r4[j].y, c);
            c = fmaf(m.z, r4[j].z, c); c = fmaf(m.w, r4[j].w, c);
        }
#pragma unroll
        for (int o = 4; o; o >>= 1) {         // reduce over s (8 lanes)
            a += __shfl_xor_sync(0xffffffffu, a, o);
            c += __shfl_xor_sync(0xffffffffu, c, o);
        }
        if (s == 0) { sd1[r0] = a; sd2[r0] = c; }
    }

    // qv = v . rq
    float qp = (t < MEM_D) ? g_v[b * MEM_D + t] * srq[t] : 0.0f;
    __syncthreads();                          // publish sd1/sd2
    const float qv = blockSum(qp, sred);

    // ---- local write-softmax partials (2 elems per thread) ----
    const float m1 = blockMax(fmaxf(sd1[t], sd1[t + 256]), sred);
    const float z1 = blockSum(__expf(sd1[t] - m1) + __expf(sd1[t + 256] - m1),
                              sred);

    // ---- cross-chunk combine #1 ----
    if (t == 0) {
        *(volatile float*)&g_pm1[bi] = m1;
        *(volatile float*)&g_pz1[bi] = z1;
        __threadfence();
        atomicAdd(&g_cnt1[b], 1);
        while (atomicAdd(&g_cnt1[b], 0) < CPB) __nanosleep(32);
        __threadfence();
    }
    __syncthreads();
    if (t < 32) {
        const float pm = (t < CPB) ? *(volatile float*)&g_pm1[b * CPB + t] : -1e30f;
        const float pz = (t < CPB) ? *(volatile float*)&g_pz1[b * CPB + t] : 0.0f;
        const float M  = warpMax(pm);
        const float Z  = warpSum(pz * __expf(pm - M));
        if (t == 0) { sbc[0] = M; sbc[1] = 1.0f / Z; }
    }
    __syncthreads();
    const float M1 = sbc[0], invZ1 = sbc[1];

    // ---- ww, read-logits; local read-softmax partials ----
    float m2l = -1e30f;
#pragma unroll
    for (int i = 0; i < 2; i++) {
        const int n = t + i * 256;
        const float ww = __expf(sd1[n] - M1) * invZ1;
        const float d2v = sd2[n];
        const float rl = d2v - ww * (d2v - qv);
        sd1[n] = ww;
        sd2[n] = rl;
        m2l = fmaxf(m2l, rl);
    }
    const float m2 = blockMax(m2l, sred);
    float lz2 = 0.0f, ls2 = 0.0f;
#pragma unroll
    for (int i = 0; i < 2; i++) {
        const int n = t + i * 256;
        const float e = __expf(sd2[n] - m2);
        lz2 += e;
        ls2 += e * sd1[n];
    }
    const float z2 = blockSum(lz2, sred);
    const float s2 = blockSum(ls2, sred);

    // ---- cross-chunk combine #2 ----
    if (t == 0) {
        *(volatile float*)&g_pm2[bi] = m2;
        *(volatile float*)&g_pz2[bi] = z2;
        *(volatile float*)&g_ps2[bi] = s2;
        __threadfence();
        atomicAdd(&g_cnt2[b], 1);
        while (atomicAdd(&g_cnt2[b], 0) < CPB) __nanosleep(32);
        __threadfence();
    }
    __syncthreads();
    if (t < 32) {
        const float pm = (t < CPB) ? *(volatile float*)&g_pm2[b * CPB + t] : -1e30f;
        const float pz = (t < CPB) ? *(volatile float*)&g_pz2[b * CPB + t] : 0.0f;
        const float ps = (t < CPB) ? *(volatile float*)&g_ps2[b * CPB + t] : 0.0f;
        const float M  = warpMax(pm);
        const float e  = __expf(pm - M);
        const float Z  = warpSum(pz * e);
        const float S  = warpSum(ps * e);
        if (t == 0) {
            sbc[0] = M; sbc[1] = 1.0f / Z;
            if (ch == 0) g_s[b] = S / Z;
        }
    }
    __syncthreads();
    const float M2 = sbc[0], invZ2 = sbc[1];
    __syncthreads();

    // ---- c_n = rw_n * (1 - ww_n) ----
#pragma unroll
    for (int i = 0; i < 2; i++) {
        const int n = t + i * 256;
        sd1[n] = __expf(sd2[n] - M2) * invZ2 * (1.0f - sd1[n]);
    }
    __syncthreads();

    // ---- Phase 2: weighted re-read, REVERSE order + streaming loads ----
    float4 acc[4];
#pragma unroll
    for (int j = 0; j < 4; j++) acc[j] = make_float4(0.f, 0.f, 0.f, 0.f);
#pragma unroll 2
    for (int it = 15; it >= 0; it--) {
        const int r0 = it * 32 + w * 4 + rsub;
        const float cv = sd1[r0];
        const float4* grow = mb + (size_t)r0 * 32;
#pragma unroll
        for (int j = 0; j < 4; j++) {
            const float4 m = __ldcs(grow + j * 8 + s);
            acc[j].x = fmaf(cv, m.x, acc[j].x);
            acc[j].y = fmaf(cv, m.y, acc[j].y);
            acc[j].z = fmaf(cv, m.z, acc[j].z);
            acc[j].w = fmaf(cv, m.w, acc[j].w);
        }
    }
    // reduce across the 4 row-subgroups (lanes xor 8, 16)
#pragma unroll
    for (int o = 8; o <= 16; o <<= 1) {
#pragma unroll
        for (int j = 0; j < 4; j++) {
            acc[j].x += __shfl_xor_sync(0xffffffffu, acc[j].x, o);
            acc[j].y += __shfl_xor_sync(0xffffffffu, acc[j].y, o);
            acc[j].z += __shfl_xor_sync(0xffffffffu, acc[j].z, o);
            acc[j].w += __shfl_xor_sync(0xffffffffu, acc[j].w, o);
        }
    }
    if (rsub == 0) {
#pragma unroll
        for (int j = 0; j < 4; j++) racc[w * 32 + j * 8 + s] = acc[j];
    }
    __syncthreads();
    if (t < 32) {
        float4 ssum = racc[t];
#pragma unroll
        for (int w2 = 1; w2 < 8; w2++) {
            const float4 u = racc[w2 * 32 + t];
            ssum.x += u.x; ssum.y += u.y; ssum.z += u.z; ssum.w += u.w;
        }
        reinterpret_cast<float4*>(g_rop + (size_t)bi * MEM_D)[t] = ssum;
    }
}

// ---------------------------------------------------------------------------
// Kernel 3: sum chunk partials, add s*v, final projection; reset counters.
// grid 64, block 512 (2 threads per output, K halves).
// ---------------------------------------------------------------------------
__global__ void __launch_bounds__(512)
out_kernel(const float* __restrict__ Wro,
           const float* __restrict__ bro,
           float* __restrict__ out) {
    const int b = blockIdx.x;
    const int t = threadIdx.x;               // 0..511
    __shared__ float sr[MEM_D];
    __shared__ float so[512];
    if (t < MEM_D) {
        float acc = g_s[b] * g_v[b * MEM_D + t];
#pragma unroll
        for (int c = 0; c < CPB; c++)
            acc += g_rop[((size_t)b * CPB + c) * MEM_D + t];
        sr[t] = acc;
    }
    if (t == 0) { g_cnt1[b] = 0; g_cnt2[b] = 0; }   // reset for next replay
    __syncthreads();

    const int o = t & 255;
    const int h = t >> 8;
    float acc = 0.0f;
    const int d0 = h * 64;
#pragma unroll 8
    for (int d = 0; d < 64; d++)
        acc = fmaf(sr[d0 + d], Wro[(d0 + d) * IN_D + o], acc);
    so[t] = acc;
    __syncthreads();
    if (t < IN_D)
        out[b * IN_D + t] = so[t] + so[256 + t] + bro[t];
}

// ---------------------------------------------------------------------------
extern "C" void kernel_launch(void* const* d_in, const int* in_sizes, int n_in,
                              void* d_out, int out_size) {
    const float* x   = (const float*)d_in[0];
    const float* mem = (const float*)d_in[1];
    const float* Ww  = (const float*)d_in[2];
    const float* bw  = (const float*)d_in[3];
    const float* Wq  = (const float*)d_in[4];
    const float* bq  = (const float*)d_in[5];
    const float* Wr  = (const float*)d_in[6];
    const float* br  = (const float*)d_in[7];
    const float* Wro = (const float*)d_in[8];
    const float* bro = (const float*)d_in[9];
    float* out = (float*)d_out;

    proj_kernel<<<24, 256>>>(x, Ww, bw, Wq, bq, Wr, br);
    fused_kernel<<<BATCH * CPB, 256>>>(mem);
    out_kernel<<<BATCH, 512>>>(Wro, bro, out);
}

// round 7
// speedup vs baseline: 1.4782x; 1.4782x over previous
#include <cuda_runtime.h>
#include <math.h>

// Problem constants
#define BATCH   64
#define IN_D    256
#define MEM_D   128
#define NSLOT   4096
#define CPB     8                  // chunks (blocks) per batch -> single wave
#define CHUNK   (NSLOT / CPB)      // 512 rows per block
#define KQ      4                  // K quarters in proj

// -------- scratch (no device allocations allowed) --------
__device__ float g_pp[3 * BATCH * KQ * MEM_D]; // proj partials [m][b][kq][o]
__device__ float g_v [BATCH * MEM_D];          // finalized v (written by fused ch==0)
__device__ float g_s [BATCH];
__device__ float g_rop[BATCH * CPB * MEM_D];   // per-chunk read_out partials

__device__ float g_pm1[BATCH * CPB];
__device__ float g_pz1[BATCH * CPB];
__device__ float g_pm2[BATCH * CPB];
__device__ float g_pz2[BATCH * CPB];
__device__ float g_ps2[BATCH * CPB];
__device__ int   g_cnt1[BATCH];                // zero-init; reset by out_kernel
__device__ int   g_cnt2[BATCH];

__device__ __forceinline__ float warpSum(float v) {
#pragma unroll
    for (int o = 16; o; o >>= 1) v += __shfl_xor_sync(0xffffffffu, v, o);
    return v;
}
__device__ __forceinline__ float warpMax(float v) {
#pragma unroll
    for (int o = 16; o; o >>= 1) v = fmaxf(v, __shfl_xor_sync(0xffffffffu, v, o));
    return v;
}
// block reduce for 256 threads (8 warps)
__device__ __forceinline__ float blockSum(float v, float* sred) {
    v = warpSum(v);
    if ((threadIdx.x & 31) == 0) sred[threadIdx.x >> 5] = v;
    __syncthreads();
    float r = sred[0];
#pragma unroll
    for (int i = 1; i < 8; i++) r += sred[i];
    __syncthreads();
    return r;
}
__device__ __forceinline__ float blockMax(float v, float* sred) {
    v = warpMax(v);
    if ((threadIdx.x & 31) == 0) sred[threadIdx.x >> 5] = v;
    __syncthreads();
    float r = sred[0];
#pragma unroll
    for (int i = 1; i < 8; i++) r = fmaxf(r, sred[i]);
    __syncthreads();
    return r;
}

// ---------------------------------------------------------------------------
// Kernel 1: projection PARTIALS, maximum parallelism.
// grid = 768 (3 matrices x 64 batches x 4 K-quarters), block 128.
// Thread t computes a 64-term partial dot for output column t.
// Consumers (fused kernel) sum the 4 partials + bias.
// ---------------------------------------------------------------------------
__global__ void __launch_bounds__(128)
proj_kernel(const float* __restrict__ x,
            const float* __restrict__ Ww,
            const float* __restrict__ Wq,
            const float* __restrict__ Wr) {
    const int m   = blockIdx.x >> 8;          // 0..2
    const int rem = blockIdx.x & 255;
    const int b   = rem >> 2;                 // 0..63
    const int kq  = rem & 3;                  // K quarter
    const int t   = threadIdx.x;              // 0..127 (output column)

    const float* W = (m == 0) ? Ww : ((m == 1) ? Wq : Wr);
    const int k0 = kq * 64;

    __shared__ float sx[64];
    if (t < 64) sx[t] = x[b * IN_D + k0 + t];
    __syncthreads();

    float acc = 0.0f;
#pragma unroll 8
    for (int k = 0; k < 64; k++)
        acc = fmaf(sx[k], W[(k0 + k) * MEM_D + t], acc);

    g_pp[(((m * BATCH) + b) * KQ + kq) * MEM_D + t] = acc;
}

// ---------------------------------------------------------------------------
// Kernel 2: FUSED dots + dual-softmax + accumulation, SINGLE WAVE.
// grid = 512 (64 x 8 chunks), block 256, 4 blocks/SM -> all resident.
// Prologue: finalize v/wq/rq from the 4 K-quarter partials (+bias).
// Phase 1 streams the 256KB slice (coalesced, fills L2); phase 2 re-reads it
// in REVERSE order (newest-first) with __ldcs (evict-first).
// Counters assumed 0 on entry (reset by out_kernel for next replay).
// ---------------------------------------------------------------------------
__global__ void __launch_bounds__(256, 4)
fused_kernel(const float* __restrict__ mem,
             const float* __restrict__ bw,
             const float* __restrict__ bq,
             const float* __restrict__ br) {
    const int b  = blockIdx.x >> 3;
    const int ch = blockIdx.x & 7;
    const int bi = blockIdx.x;
    const int t  = threadIdx.x;
    const int lane = t & 31, w = t >> 5;      // 8 warps
    const int s = lane & 7, rsub = lane >> 3; // quarter-warp layout

    __shared__ float  sd1[CHUNK];             // d1 -> ww -> c
    __shared__ float  sd2[CHUNK];             // d2 -> rl
    __shared__ float  swq[MEM_D];
    __shared__ float  srq[MEM_D];
    __shared__ float  sv [MEM_D];
    __shared__ float  sred[8];
    __shared__ float  sbc[2];
    __shared__ float4 racc[256];

    if (t < MEM_D) {
        const float* pv = g_pp + ((0 * BATCH + b) * KQ) * MEM_D + t;
        const float* pq = g_pp + ((1 * BATCH + b) * KQ) * MEM_D + t;
        const float* pr = g_pp + ((2 * BATCH + b) * KQ) * MEM_D + t;
        sv [t] = pv[0] + pv[MEM_D] + pv[2 * MEM_D] + pv[3 * MEM_D] + bw[t];
        swq[t] = pq[0] + pq[MEM_D] + pq[2 * MEM_D] + pq[3 * MEM_D] + bq[t];
        srq[t] = pr[0] + pr[MEM_D] + pr[2 * MEM_D] + pr[3 * MEM_D] + br[t];
        if (ch == 0) g_v[b * MEM_D + t] = sv[t];   // publish for out_kernel
    }
    __syncthreads();

    // per-thread query slices (cols (j*8+s)*4 .. +3)
    float4 q4[4], r4[4];
#pragma unroll
    for (int j = 0; j < 4; j++) {
        q4[j] = reinterpret_cast<const float4*>(swq)[j * 8 + s];
        r4[j] = reinterpret_cast<const float4*>(srq)[j * 8 + s];
    }

    const float4* mb = reinterpret_cast<const float4*>(mem) +
                       ((size_t)b * NSLOT + (size_t)ch * CHUNK) * 32;

    // ---- Phase 1: coalesced dots d1 = mem.wq, d2 = mem.rq ----
#pragma unroll 2
    for (int it = 0; it < 16; it++) {
        const int r0 = it * 32 + w * 4 + rsub;
        const float4* grow = mb + (size_t)r0 * 32;
        float a = 0.0f, c = 0.0f;
#pragma unroll
        for (int j = 0; j < 4; j++) {
            const float4 m = grow[j * 8 + s];
            a = fmaf(m.x, q4[j].x, a); a = fmaf(m.y, q4[j].y, a);
            a = fmaf(m.z, q4[j].z, a); a = fmaf(m.w, q4[j].w, a);
            c = fmaf(m.x, r4[j].x, c); c = fmaf(m.y, r4[j].y, c);
            c = fmaf(m.z, r4[j].z, c); c = fmaf(m.w, r4[j].w, c);
        }
#pragma unroll
        for (int o = 4; o; o >>= 1) {         // reduce over s (8 lanes)
            a += __shfl_xor_sync(0xffffffffu, a, o);
            c += __shfl_xor_sync(0xffffffffu, c, o);
        }
        if (s == 0) { sd1[r0] = a; sd2[r0] = c; }
    }

    // qv = v . rq
    float qp = (t < MEM_D) ? sv[t] * srq[t] : 0.0f;
    __syncthreads();                          // publish sd1/sd2
    const float qv = blockSum(qp, sred);

    // ---- local write-softmax partials (2 elems per thread) ----
    const float m1 = blockMax(fmaxf(sd1[t], sd1[t + 256]), sred);
    const float z1 = blockSum(__expf(sd1[t] - m1) + __expf(sd1[t + 256] - m1),
                              sred);

    // ---- cross-chunk combine #1 ----
    if (t == 0) {
        *(volatile float*)&g_pm1[bi] = m1;
        *(volatile float*)&g_pz1[bi] = z1;
        __threadfence();
        atomicAdd(&g_cnt1[b], 1);
        while (atomicAdd(&g_cnt1[b], 0) < CPB) __nanosleep(32);
        __threadfence();
    }
    __syncthreads();
    if (t < 32) {
        const float pm = (t < CPB) ? *(volatile float*)&g_pm1[b * CPB + t] : -1e30f;
        const float pz = (t < CPB) ? *(volatile float*)&g_pz1[b * CPB + t] : 0.0f;
        const float M  = warpMax(pm);
        const float Z  = warpSum(pz * __expf(pm - M));
        if (t == 0) { sbc[0] = M; sbc[1] = 1.0f / Z; }
    }
    __syncthreads();
    const float M1 = sbc[0], invZ1 = sbc[1];

    // ---- ww, read-logits; local read-softmax partials ----
    float m2l = -1e30f;
#pragma unroll
    for (int i = 0; i < 2; i++) {
        const int n = t + i * 256;
        const float ww = __expf(sd1[n] - M1) * invZ1;
        const float d2v = sd2[n];
        const float rl = d2v - ww * (d2v - qv);
        sd1[n] = ww;
        sd2[n] = rl;
        m2l = fmaxf(m2l, rl);
    }
    const float m2 = blockMax(m2l, sred);
    float lz2 = 0.0f, ls2 = 0.0f;
#pragma unroll
    for (int i = 0; i < 2; i++) {
        const int n = t + i * 256;
        const float e = __expf(sd2[n] - m2);
        lz2 += e;
        ls2 += e * sd1[n];
    }
    const float z2 = blockSum(lz2, sred);
    const float s2 = blockSum(ls2, sred);

    // ---- cross-chunk combine #2 ----
    if (t == 0) {
        *(volatile float*)&g_pm2[bi] = m2;
        *(volatile float*)&g_pz2[bi] = z2;
        *(volatile float*)&g_ps2[bi] = s2;
        __threadfence();
        atomicAdd(&g_cnt2[b], 1);
        while (atomicAdd(&g_cnt2[b], 0) < CPB) __nanosleep(32);
        __threadfence();
    }
    __syncthreads();
    if (t < 32) {
        const float pm = (t < CPB) ? *(volatile float*)&g_pm2[b * CPB + t] : -1e30f;
        const float pz = (t < CPB) ? *(volatile float*)&g_pz2[b * CPB + t] : 0.0f;
        const float ps = (t < CPB) ? *(volatile float*)&g_ps2[b * CPB + t] : 0.0f;
        const float M  = warpMax(pm);
        const float e  = __expf(pm - M);
        const float Z  = warpSum(pz * e);
        const float S  = warpSum(ps * e);
        if (t == 0) {
            sbc[0] = M; sbc[1] = 1.0f / Z;
            if (ch == 0) g_s[b] = S / Z;
        }
    }
    __syncthreads();
    const float M2 = sbc[0], invZ2 = sbc[1];
    __syncthreads();

    // ---- c_n = rw_n * (1 - ww_n) ----
#pragma unroll
    for (int i = 0; i < 2; i++) {
        const int n = t + i * 256;
        sd1[n] = __expf(sd2[n] - M2) * invZ2 * (1.0f - sd1[n]);
    }
    __syncthreads();

    // ---- Phase 2: weighted re-read, REVERSE order + streaming loads ----
    float4 acc[4];
#pragma unroll
    for (int j = 0; j < 4; j++) acc[j] = make_float4(0.f, 0.f, 0.f, 0.f);
#pragma unroll 2
    for (int it = 15; it >= 0; it--) {
        const int r0 = it * 32 + w * 4 + rsub;
        const float cv = sd1[r0];
        const float4* grow = mb + (size_t)r0 * 32;
#pragma unroll
        for (int j = 0; j < 4; j++) {
            const float4 m = __ldcs(grow + j * 8 + s);
            acc[j].x = fmaf(cv, m.x, acc[j].x);
            acc[j].y = fmaf(cv, m.y, acc[j].y);
            acc[j].z = fmaf(cv, m.z, acc[j].z);
            acc[j].w = fmaf(cv, m.w, acc[j].w);
        }
    }
    // reduce across the 4 row-subgroups (lanes xor 8, 16)
#pragma unroll
    for (int o = 8; o <= 16; o <<= 1) {
#pragma unroll
        for (int j = 0; j < 4; j++) {
            acc[j].x += __shfl_xor_sync(0xffffffffu, acc[j].x, o);
            acc[j].y += __shfl_xor_sync(0xffffffffu, acc[j].y, o);
            acc[j].z += __shfl_xor_sync(0xffffffffu, acc[j].z, o);
            acc[j].w += __shfl_xor_sync(0xffffffffu, acc[j].w, o);
        }
    }
    if (rsub == 0) {
#pragma unroll
        for (int j = 0; j < 4; j++) racc[w * 32 + j * 8 + s] = acc[j];
    }
    __syncthreads();
    if (t < 32) {
        float4 ssum = racc[t];
#pragma unroll
        for (int w2 = 1; w2 < 8; w2++) {
            const float4 u = racc[w2 * 32 + t];
            ssum.x += u.x; ssum.y += u.y; ssum.z += u.z; ssum.w += u.w;
        }
        reinterpret_cast<float4*>(g_rop + (size_t)bi * MEM_D)[t] = ssum;
    }
}

// ---------------------------------------------------------------------------
// Kernel 3: sum chunk partials, add s*v, final projection; reset counters.
// grid 64, block 512 (2 threads per output, K halves).
// ---------------------------------------------------------------------------
__global__ void __launch_bounds__(512)
out_kernel(const float* __restrict__ Wro,
           const float* __restrict__ bro,
           float* __restrict__ out) {
    const int b = blockIdx.x;
    const int t = threadIdx.x;               // 0..511
    __shared__ float sr[MEM_D];
    __shared__ float so[512];
    if (t < MEM_D) {
        float acc = g_s[b] * g_v[b * MEM_D + t];
#pragma unroll
        for (int c = 0; c < CPB; c++)
            acc += g_rop[((size_t)b * CPB + c) * MEM_D + t];
        sr[t] = acc;
    }
    if (t == 0) { g_cnt1[b] = 0; g_cnt2[b] = 0; }   // reset for next replay
    __syncthreads();

    const int o = t & 255;
    const int h = t >> 8;
    float acc = 0.0f;
    const int d0 = h * 64;
#pragma unroll 8
    for (int d = 0; d < 64; d++)
        acc = fmaf(sr[d0 + d], Wro[(d0 + d) * IN_D + o], acc);
    so[t] = acc;
    __syncthreads();
    if (t < IN_D)
        out[b * IN_D + t] = so[t] + so[256 + t] + bro[t];
}

// ---------------------------------------------------------------------------
extern "C" void kernel_launch(void* const* d_in, const int* in_sizes, int n_in,
                              void* d_out, int out_size) {
    const float* x   = (const float*)d_in[0];
    const float* mem = (const float*)d_in[1];
    const float* Ww  = (const float*)d_in[2];
    const float* bw  = (const float*)d_in[3];
    const float* Wq  = (const float*)d_in[4];
    const float* bq  = (const float*)d_in[5];
    const float* Wr  = (const float*)d_in[6];
    const float* br  = (const float*)d_in[7];
    const float* Wro = (const float*)d_in[8];
    const float* bro = (const float*)d_in[9];
    float* out = (float*)d_out;

    proj_kernel<<<3 * BATCH * KQ, 128>>>(x, Ww, Wq, Wr);
    fused_kernel<<<BATCH * CPB, 256>>>(mem, bw, bq, br);
    out_kernel<<<BATCH, 512>>>(Wro, bro, out);
}

// round 8
// speedup vs baseline: 1.5347x; 1.0382x over previous
#include <cuda_runtime.h>
#include <math.h>

// Problem constants
#define BATCH   64
#define IN_D    256
#define MEM_D   128
#define NSLOT   4096
#define CPB     8                  // chunks (blocks) per batch -> single wave
#define CHUNK   (NSLOT / CPB)      // 512 rows per block
#define KQ      4                  // K quarters in proj

// -------- scratch (no device allocations allowed) --------
__device__ float g_pp[3 * BATCH * KQ * MEM_D]; // proj partials [m][b][kq][o]
__device__ float g_v [BATCH * MEM_D];          // finalized v (written by fused ch==0)
__device__ float g_s [BATCH];
__device__ float g_rop[BATCH * CPB * MEM_D];   // per-chunk read_out partials

__device__ float g_pm1[BATCH * CPB];
__device__ float g_pz1[BATCH * CPB];
__device__ float g_pm2[BATCH * CPB];
__device__ float g_pz2[BATCH * CPB];
__device__ float g_ps2[BATCH * CPB];
__device__ int   g_cnt1[BATCH];                // zero-init; reset by out_kernel
__device__ int   g_cnt2[BATCH];

__device__ __forceinline__ float warpSum(float v) {
#pragma unroll
    for (int o = 16; o; o >>= 1) v += __shfl_xor_sync(0xffffffffu, v, o);
    return v;
}
__device__ __forceinline__ float warpMax(float v) {
#pragma unroll
    for (int o = 16; o; o >>= 1) v = fmaxf(v, __shfl_xor_sync(0xffffffffu, v, o));
    return v;
}
// block reduce for 256 threads (8 warps)
__device__ __forceinline__ float blockSum(float v, float* sred) {
    v = warpSum(v);
    if ((threadIdx.x & 31) == 0) sred[threadIdx.x >> 5] = v;
    __syncthreads();
    float r = sred[0];
#pragma unroll
    for (int i = 1; i < 8; i++) r += sred[i];
    __syncthreads();
    return r;
}
__device__ __forceinline__ float blockMax(float v, float* sred) {
    v = warpMax(v);
    if ((threadIdx.x & 31) == 0) sred[threadIdx.x >> 5] = v;
    __syncthreads();
    float r = sred[0];
#pragma unroll
    for (int i = 1; i < 8; i++) r = fmaxf(r, sred[i]);
    __syncthreads();
    return r;
}

// ---------------------------------------------------------------------------
// Kernel 1: projection PARTIALS. grid = 768 (3 x 64 x 4 K-quarters), blk 128.
// Four independent accumulator chains per thread (ILP).
// ---------------------------------------------------------------------------
__global__ void __launch_bounds__(128)
proj_kernel(const float* __restrict__ x,
            const float* __restrict__ Ww,
            const float* __restrict__ Wq,
            const float* __restrict__ Wr) {
    const int m   = blockIdx.x >> 8;          // 0..2
    const int rem = blockIdx.x & 255;
    const int b   = rem >> 2;                 // 0..63
    const int kq  = rem & 3;                  // K quarter
    const int t   = threadIdx.x;              // 0..127 (output column)

    const float* W = (m == 0) ? Ww : ((m == 1) ? Wq : Wr);
    const int k0 = kq * 64;

    __shared__ float sx[64];
    if (t < 64) sx[t] = x[b * IN_D + k0 + t];
    __syncthreads();

    float a0 = 0.f, a1 = 0.f, a2 = 0.f, a3 = 0.f;
    const float* Wc = W + (size_t)k0 * MEM_D + t;
#pragma unroll
    for (int k = 0; k < 64; k += 4) {
        a0 = fmaf(sx[k + 0], Wc[(k + 0) * MEM_D], a0);
        a1 = fmaf(sx[k + 1], Wc[(k + 1) * MEM_D], a1);
        a2 = fmaf(sx[k + 2], Wc[(k + 2) * MEM_D], a2);
        a3 = fmaf(sx[k + 3], Wc[(k + 3) * MEM_D], a3);
    }
    g_pp[(((m * BATCH) + b) * KQ + kq) * MEM_D + t] = (a0 + a1) + (a2 + a3);
}

// ---------------------------------------------------------------------------
// Kernel 2: FUSED dots + dual-softmax + accumulation, SINGLE WAVE.
// grid = 512 (64 x 8 chunks), block 256, 4 blocks/SM -> all resident.
// Barrier-2 is split: arrive BEFORE the phase-2 re-read (local-scale trick:
// c'_n = e^{rl_n - m2_loc}(1-ww_n), rescale by e^{m2_loc - M2}/Z2 after),
// wait AFTER it -> the global sync cost overlaps the memory work and the
// read->re-read gap shrinks (better L2 residency).
// ---------------------------------------------------------------------------
__global__ void __launch_bounds__(256, 4)
fused_kernel(const float* __restrict__ mem,
             const float* __restrict__ bw,
             const float* __restrict__ bq,
             const float* __restrict__ br) {
    const int b  = blockIdx.x >> 3;
    const int ch = blockIdx.x & 7;
    const int bi = blockIdx.x;
    const int t  = threadIdx.x;
    const int lane = t & 31, w = t >> 5;      // 8 warps
    const int s = lane & 7, rsub = lane >> 3; // quarter-warp layout

    __shared__ float  sd1[CHUNK];             // d1 -> ww -> c'
    __shared__ float  sd2[CHUNK];             // d2 -> rl
    __shared__ float  swq[MEM_D];
    __shared__ float  srq[MEM_D];
    __shared__ float  sv [MEM_D];
    __shared__ float  sred[8];
    __shared__ float  sbc[2];
    __shared__ float4 racc[256];

    if (t < MEM_D) {
        const float* pv = g_pp + ((0 * BATCH + b) * KQ) * MEM_D + t;
        const float* pq = g_pp + ((1 * BATCH + b) * KQ) * MEM_D + t;
        const float* pr = g_pp + ((2 * BATCH + b) * KQ) * MEM_D + t;
        sv [t] = pv[0] + pv[MEM_D] + pv[2 * MEM_D] + pv[3 * MEM_D] + bw[t];
        swq[t] = pq[0] + pq[MEM_D] + pq[2 * MEM_D] + pq[3 * MEM_D] + bq[t];
        srq[t] = pr[0] + pr[MEM_D] + pr[2 * MEM_D] + pr[3 * MEM_D] + br[t];
        if (ch == 0) g_v[b * MEM_D + t] = sv[t];   // publish for out_kernel
    }
    __syncthreads();

    // per-thread query slices (cols (j*8+s)*4 .. +3)
    float4 q4[4], r4[4];
#pragma unroll
    for (int j = 0; j < 4; j++) {
        q4[j] = reinterpret_cast<const float4*>(swq)[j * 8 + s];
        r4[j] = reinterpret_cast<const float4*>(srq)[j * 8 + s];
    }

    const float4* mb = reinterpret_cast<const float4*>(mem) +
                       ((size_t)b * NSLOT + (size_t)ch * CHUNK) * 32;

    // ---- Phase 1: coalesced dots d1 = mem.wq, d2 = mem.rq ----
#pragma unroll 2
    for (int it = 0; it < 16; it++) {
        const int r0 = it * 32 + w * 4 + rsub;
        const float4* grow = mb + (size_t)r0 * 32;
        float a = 0.0f, c = 0.0f;
#pragma unroll
        for (int j = 0; j < 4; j++) {
            const float4 m = grow[j * 8 + s];
            a = fmaf(m.x, q4[j].x, a); a = fmaf(m.y, q4[j].y, a);
            a = fmaf(m.z, q4[j].z, a); a = fmaf(m.w, q4[j].w, a);
            c = fmaf(m.x, r4[j].x, c); c = fmaf(m.y, r4[j].y, c);
            c = fmaf(m.z, r4[j].z, c); c = fmaf(m.w, r4[j].w, c);
        }
#pragma unroll
        for (int o = 4; o; o >>= 1) {         // reduce over s (8 lanes)
            a += __shfl_xor_sync(0xffffffffu, a, o);
            c += __shfl_xor_sync(0xffffffffu, c, o);
        }
        if (s == 0) { sd1[r0] = a; sd2[r0] = c; }
    }

    // qv = v . rq
    float qp = (t < MEM_D) ? sv[t] * srq[t] : 0.0f;
    __syncthreads();                          // publish sd1/sd2
    const float qv = blockSum(qp, sred);

    // ---- local write-softmax partials (2 elems per thread) ----
    const float m1 = blockMax(fmaxf(sd1[t], sd1[t + 256]), sred);
    const float z1 = blockSum(__expf(sd1[t] - m1) + __expf(sd1[t + 256] - m1),
                              sred);

    // ---- cross-chunk combine #1 (full wait: ww needs global M1/Z1) ----
    if (t == 0) {
        *(volatile float*)&g_pm1[bi] = m1;
        *(volatile float*)&g_pz1[bi] = z1;
        __threadfence();
        atomicAdd(&g_cnt1[b], 1);
        while (atomicAdd(&g_cnt1[b], 0) < CPB) __nanosleep(32);
        __threadfence();
    }
    __syncthreads();
    if (t < 32) {
        const float pm = (t < CPB) ? *(volatile float*)&g_pm1[b * CPB + t] : -1e30f;
        const float pz = (t < CPB) ? *(volatile float*)&g_pz1[b * CPB + t] : 0.0f;
        const float M  = warpMax(pm);
        const float Z  = warpSum(pz * __expf(pm - M));
        if (t == 0) { sbc[0] = M; sbc[1] = 1.0f / Z; }
    }
    __syncthreads();
    const float M1 = sbc[0], invZ1 = sbc[1];

    // ---- ww (exact), read-logits; local read-softmax partials ----
    float m2l = -1e30f;
#pragma unroll
    for (int i = 0; i < 2; i++) {
        const int n = t + i * 256;
        const float ww = __expf(sd1[n] - M1) * invZ1;
        const float d2v = sd2[n];
        const float rl = d2v - ww * (d2v - qv);
        sd1[n] = ww;
        sd2[n] = rl;
        m2l = fmaxf(m2l, rl);
    }
    const float m2 = blockMax(m2l, sred);
    float lz2 = 0.0f, ls2 = 0.0f;
#pragma unroll
    for (int i = 0; i < 2; i++) {
        const int n = t + i * 256;
        const float e = __expf(sd2[n] - m2);
        lz2 += e;
        ls2 += e * sd1[n];
    }
    const float z2 = blockSum(lz2, sred);
    const float s2 = blockSum(ls2, sred);

    // ---- barrier 2: ARRIVE ONLY (wait deferred past phase 2) ----
    if (t == 0) {
        *(volatile float*)&g_pm2[bi] = m2;
        *(volatile float*)&g_pz2[bi] = z2;
        *(volatile float*)&g_ps2[bi] = s2;
        __threadfence();
        atomicAdd(&g_cnt2[b], 1);
    }

    // ---- c'_n = e^{rl_n - m2_loc} * (1 - ww_n)  (locally-scaled coeff) ----
#pragma unroll
    for (int i = 0; i < 2; i++) {
        const int n = t + i * 256;
        sd1[n] = __expf(sd2[n] - m2) * (1.0f - sd1[n]);
    }
    __syncthreads();

    // ---- Phase 2: weighted re-read, REVERSE order + streaming loads ----
    float4 acc[4];
#pragma unroll
    for (int j = 0; j < 4; j++) acc[j] = make_float4(0.f, 0.f, 0.f, 0.f);
#pragma unroll 2
    for (int it = 15; it >= 0; it--) {
        const int r0 = it * 32 + w * 4 + rsub;
        const float cv = sd1[r0];
        const float4* grow = mb + (size_t)r0 * 32;
#pragma unroll
        for (int j = 0; j < 4; j++) {
            const float4 m = __ldcs(grow + j * 8 + s);
            acc[j].x = fmaf(cv, m.x, acc[j].x);
            acc[j].y = fmaf(cv, m.y, acc[j].y);
            acc[j].z = fmaf(cv, m.z, acc[j].z);
            acc[j].w = fmaf(cv, m.w, acc[j].w);
        }
    }

    // ---- barrier 2: WAIT + combine (overlapped with peers' phase 2) ----
    if (t == 0) {
        while (atomicAdd(&g_cnt2[b], 0) < CPB) __nanosleep(32);
        __threadfence();
    }
    __syncthreads();
    if (t < 32) {
        const float pm = (t < CPB) ? *(volatile float*)&g_pm2[b * CPB + t] : -1e30f;
        const float pz = (t < CPB) ? *(volatile float*)&g_pz2[b * CPB + t] : 0.0f;
        const float ps = (t < CPB) ? *(volatile float*)&g_ps2[b * CPB + t] : 0.0f;
        const float M  = warpMax(pm);
        const float e  = __expf(pm - M);
        const float Z  = warpSum(pz * e);
        const float S  = warpSum(ps * e);
        if (t == 0) {
            sbc[0] = M; sbc[1] = 1.0f / Z;
            if (ch == 0) g_s[b] = S / Z;
        }
    }
    __syncthreads();
    const float scale = __expf(m2 - sbc[0]) * sbc[1];   // e^{m2-M2}/Z2

    // reduce across the 4 row-subgroups (lanes xor 8, 16)
#pragma unroll
    for (int o = 8; o <= 16; o <<= 1) {
#pragma unroll
        for (int j = 0; j < 4; j++) {
            acc[j].x += __shfl_xor_sync(0xffffffffu, acc[j].x, o);
            acc[j].y += __shfl_xor_sync(0xffffffffu, acc[j].y, o);
            acc[j].z += __shfl_xor_sync(0xffffffffu, acc[j].z, o);
            acc[j].w += __shfl_xor_sync(0xffffffffu, acc[j].w, o);
        }
    }
    if (rsub == 0) {
#pragma unroll
        for (int j = 0; j < 4; j++) {
            acc[j].x *= scale; acc[j].y *= scale;
            acc[j].z *= scale; acc[j].w *= scale;
            racc[w * 32 + j * 8 + s] = acc[j];
        }
    }
    __syncthreads();
    if (t < 32) {
        float4 ssum = racc[t];
#pragma unroll
        for (int w2 = 1; w2 < 8; w2++) {
            const float4 u = racc[w2 * 32 + t];
            ssum.x += u.x; ssum.y += u.y; ssum.z += u.z; ssum.w += u.w;
        }
        reinterpret_cast<float4*>(g_rop + (size_t)bi * MEM_D)[t] = ssum;
    }
}

// ---------------------------------------------------------------------------
// Kernel 3: sum chunk partials, add s*v, final projection; reset counters.
// grid 64, block 512 (2 threads per output, K halves).
// ---------------------------------------------------------------------------
__global__ void __launch_bounds__(512)
out_kernel(const float* __restrict__ Wro,
           const float* __restrict__ bro,
           float* __restrict__ out) {
    const int b = blockIdx.x;
    const int t = threadIdx.x;               // 0..511
    __shared__ float sr[MEM_D];
    __shared__ float so[512];
    if (t < MEM_D) {
        float acc = g_s[b] * g_v[b * MEM_D + t];
#pragma unroll
        for (int c = 0; c < CPB; c++)
            acc += g_rop[((size_t)b * CPB + c) * MEM_D + t];
        sr[t] = acc;
    }
    if (t == 0) { g_cnt1[b] = 0; g_cnt2[b] = 0; }   // reset for next replay
    __syncthreads();

    const int o = t & 255;
    const int h = t >> 8;
    float acc = 0.0f;
    const int d0 = h * 64;
#pragma unroll 8
    for (int d = 0; d < 64; d++)
        acc = fmaf(sr[d0 + d], Wro[(d0 + d) * IN_D + o], acc);
    so[t] = acc;
    __syncthreads();
    if (t < IN_D)
        out[b * IN_D + t] = so[t] + so[256 + t] + bro[t];
}

// ---------------------------------------------------------------------------
extern "C" void kernel_launch(void* const* d_in, const int* in_sizes, int n_in,
                              void* d_out, int out_size) {
    const float* x   = (const float*)d_in[0];
    const float* mem = (const float*)d_in[1];
    const float* Ww  = (const float*)d_in[2];
    const float* bw  = (const float*)d_in[3];
    const float* Wq  = (const float*)d_in[4];
    const float* bq  = (const float*)d_in[5];
    const float* Wr  = (const float*)d_in[6];
    const float* br  = (const float*)d_in[7];
    const float* Wro = (const float*)d_in[8];
    const float* bro = (const float*)d_in[9];
    float* out = (float*)d_out;

    proj_kernel<<<3 * BATCH * KQ, 128>>>(x, Ww, Wq, Wr);
    fused_kernel<<<BATCH * CPB, 256>>>(mem, bw, bq, br);
    out_kernel<<<BATCH, 512>>>(Wro, bro, out);
}